// round 1
// baseline (speedup 1.0000x reference)
#include <cuda_runtime.h>
#include <math.h>

#define BATCH 8192
#define DIM 256
#define TILE 128
#define RCHUNK 32
#define ROWS_PER_CHUNK (BATCH / RCHUNK)

// Scratch (device globals: allocation-free per harness rules)
static __device__ float g_sim[(size_t)BATCH * BATCH];   // 256 MB
static __device__ float g_thr[BATCH];
static __device__ float g_diag[BATCH];
static __device__ float g_rowlse[BATCH];
static __device__ float g_collse[BATCH];
static __device__ float g_pm[RCHUNK * BATCH];
static __device__ float g_ps[RCHUNK * BATCH];

// ---------------------------------------------------------------------------
// K1: sim = (V @ T^T) / 0.07   -> g_sim
// 128x128 tile, 256 threads, 8x8 per-thread microtile, K-step 16
// ---------------------------------------------------------------------------
__global__ __launch_bounds__(256) void gemm_kernel(const float* __restrict__ V,
                                                   const float* __restrict__ Tm)
{
    __shared__ float As[16][TILE];
    __shared__ float Bs[16][TILE];
    const int tid = threadIdx.x;
    const int m0 = blockIdx.y * TILE;
    const int n0 = blockIdx.x * TILE;
    const int tx = tid & 15;
    const int ty = tid >> 4;
    const int mrow = ty * 8;
    const int ncol = tx * 8;

    float acc[8][8];
#pragma unroll
    for (int x = 0; x < 8; x++)
#pragma unroll
        for (int y = 0; y < 8; y++) acc[x][y] = 0.f;

    for (int k0 = 0; k0 < DIM; k0 += 16) {
#pragma unroll
        for (int q = 0; q < 2; q++) {
            int f = tid * 2 + q;
            int row = f >> 2;          // 0..127
            int kk = (f & 3) << 2;     // 0,4,8,12
            float4 va = *(const float4*)(V + (size_t)(m0 + row) * DIM + k0 + kk);
            As[kk + 0][row] = va.x; As[kk + 1][row] = va.y;
            As[kk + 2][row] = va.z; As[kk + 3][row] = va.w;
            float4 vb = *(const float4*)(Tm + (size_t)(n0 + row) * DIM + k0 + kk);
            Bs[kk + 0][row] = vb.x; Bs[kk + 1][row] = vb.y;
            Bs[kk + 2][row] = vb.z; Bs[kk + 3][row] = vb.w;
        }
        __syncthreads();
#pragma unroll
        for (int k = 0; k < 16; k++) {
            float a[8], b[8];
#pragma unroll
            for (int e = 0; e < 8; e++) a[e] = As[k][mrow + e];
#pragma unroll
            for (int e = 0; e < 8; e++) b[e] = Bs[k][ncol + e];
#pragma unroll
            for (int x = 0; x < 8; x++)
#pragma unroll
                for (int y = 0; y < 8; y++)
                    acc[x][y] = fmaf(a[x], b[y], acc[x][y]);
        }
        __syncthreads();
    }

    const float inv_t = 1.0f / 0.07f;
#pragma unroll
    for (int x = 0; x < 8; x++) {
        float* dst = g_sim + (size_t)(m0 + mrow + x) * BATCH + n0 + ncol;
        float4 w0 = make_float4(acc[x][0] * inv_t, acc[x][1] * inv_t,
                                acc[x][2] * inv_t, acc[x][3] * inv_t);
        float4 w1 = make_float4(acc[x][4] * inv_t, acc[x][5] * inv_t,
                                acc[x][6] * inv_t, acc[x][7] * inv_t);
        *(float4*)(dst) = w0;
        *(float4*)(dst + 4) = w1;
    }
}

// ---------------------------------------------------------------------------
// K2: per row -> diag, thr (4th largest off-diag), rowLSE of weighted logits
// ---------------------------------------------------------------------------
__device__ __forceinline__ void top4_insert(float x, float& t0, float& t1,
                                            float& t2, float& t3)
{
    if (x > t3) {
        if (x > t0)      { t3 = t2; t2 = t1; t1 = t0; t0 = x; }
        else if (x > t1) { t3 = t2; t2 = t1; t1 = x; }
        else if (x > t2) { t3 = t2; t2 = x; }
        else             { t3 = x; }
    }
}

__global__ __launch_bounds__(256) void rowstats_kernel()
{
    __shared__ float row[BATCH];                      // 32 KB
    __shared__ float r0s[256], r1s[256], r2s[256], r3s[256];
    __shared__ float red[256];
    const int i = blockIdx.x;
    const int tid = threadIdx.x;
    const float* src = g_sim + (size_t)i * BATCH;
    for (int j = tid; j < BATCH; j += 256) row[j] = src[j];
    __syncthreads();

    const float diag = row[i];

    // local top-4 (diag excluded)
    float t0 = -3e38f, t1 = -3e38f, t2 = -3e38f, t3 = -3e38f;
    for (int j = tid; j < BATCH; j += 256) {
        float x = (j == i) ? -3.0e38f : row[j];
        top4_insert(x, t0, t1, t2, t3);
    }
    r0s[tid] = t0; r1s[tid] = t1; r2s[tid] = t2; r3s[tid] = t3;
    __syncthreads();
    for (int s = 128; s > 0; s >>= 1) {
        if (tid < s) {
            float u0 = r0s[tid], u1 = r1s[tid], u2 = r2s[tid], u3 = r3s[tid];
            top4_insert(r0s[tid + s], u0, u1, u2, u3);
            top4_insert(r1s[tid + s], u0, u1, u2, u3);
            top4_insert(r2s[tid + s], u0, u1, u2, u3);
            top4_insert(r3s[tid + s], u0, u1, u2, u3);
            r0s[tid] = u0; r1s[tid] = u1; r2s[tid] = u2; r3s[tid] = u3;
        }
        __syncthreads();
    }
    const float thr = r3s[0];

    // row max of weighted logits
    float m = -3e38f;
    for (int j = tid; j < BATCH; j += 256) {
        float x = row[j];
        float v = (j == i) ? x : ((x >= thr) ? 2.0f * x : x);
        m = fmaxf(m, v);
    }
    red[tid] = m; __syncthreads();
    for (int s = 128; s > 0; s >>= 1) {
        if (tid < s) red[tid] = fmaxf(red[tid], red[tid + s]);
        __syncthreads();
    }
    m = red[0];
    __syncthreads();

    // row sum of exp
    float ssum = 0.f;
    for (int j = tid; j < BATCH; j += 256) {
        float x = row[j];
        float v = (j == i) ? x : ((x >= thr) ? 2.0f * x : x);
        ssum += expf(v - m);
    }
    red[tid] = ssum; __syncthreads();
    for (int s = 128; s > 0; s >>= 1) {
        if (tid < s) red[tid] += red[tid + s];
        __syncthreads();
    }
    if (tid == 0) {
        g_rowlse[i] = m + logf(red[0]);
        g_diag[i] = diag;
        g_thr[i] = thr;
    }
}

// ---------------------------------------------------------------------------
// K3: partial column LSE over a 256-row chunk (online LSE per thread)
// grid: (BATCH/256 column groups, RCHUNK row chunks)
// ---------------------------------------------------------------------------
__global__ __launch_bounds__(256) void colpass_kernel()
{
    const int j = blockIdx.x * 256 + threadIdx.x;
    const int i0 = blockIdx.y * ROWS_PER_CHUNK;
    float m = -3e38f, s = 0.f;
    const float* p = g_sim + (size_t)i0 * BATCH + j;
    for (int r = 0; r < ROWS_PER_CHUNK; r++) {
        const int i = i0 + r;
        float x = *p;
        p += BATCH;
        float thr = __ldg(&g_thr[i]);                 // broadcast across block
        float v = (j == i) ? x : ((x >= thr) ? 2.0f * x : x);
        if (v > m) { s = s * expf(m - v) + 1.0f; m = v; }
        else       { s += expf(v - m); }
    }
    g_pm[blockIdx.y * BATCH + j] = m;
    g_ps[blockIdx.y * BATCH + j] = s;
}

// K3b: merge the RCHUNK partial (m,s) pairs per column
__global__ __launch_bounds__(256) void colmerge_kernel()
{
    const int j = blockIdx.x * 256 + threadIdx.x;
    float M = -3e38f;
#pragma unroll
    for (int c = 0; c < RCHUNK; c++) M = fmaxf(M, g_pm[c * BATCH + j]);
    float S = 0.f;
#pragma unroll
    for (int c = 0; c < RCHUNK; c++) S += g_ps[c * BATCH + j] * expf(g_pm[c * BATCH + j] - M);
    g_collse[j] = M + logf(S);
}

// ---------------------------------------------------------------------------
// K4: loss = sum_i [(rowLSE_i - diag_i) + (colLSE_i - diag_i)] / (2B)
// ---------------------------------------------------------------------------
__global__ __launch_bounds__(256) void finalize_kernel(float* __restrict__ out)
{
    __shared__ float red[256];
    const int tid = threadIdx.x;
    float acc = 0.f;
    for (int i = tid; i < BATCH; i += 256)
        acc += (g_rowlse[i] - g_diag[i]) + (g_collse[i] - g_diag[i]);
    red[tid] = acc; __syncthreads();
    for (int s = 128; s > 0; s >>= 1) {
        if (tid < s) red[tid] += red[tid + s];
        __syncthreads();
    }
    if (tid == 0) out[0] = red[0] / (2.0f * (float)BATCH);
}

extern "C" void kernel_launch(void* const* d_in, const int* in_sizes, int n_in,
                              void* d_out, int out_size)
{
    (void)in_sizes; (void)n_in; (void)out_size;
    const float* V  = (const float*)d_in[0];   // vision_embed [8192, 256]
    const float* Tm = (const float*)d_in[1];   // text_embed   [8192, 256]
    float* out = (float*)d_out;

    dim3 g1(BATCH / TILE, BATCH / TILE);
    gemm_kernel<<<g1, 256>>>(V, Tm);
    rowstats_kernel<<<BATCH, 256>>>();
    colpass_kernel<<<dim3(BATCH / 256, RCHUNK), 256>>>();
    colmerge_kernel<<<BATCH / 256, 256>>>();
    finalize_kernel<<<1, 256>>>(out);
}

// round 3
// speedup vs baseline: 1.5921x; 1.5921x over previous
#include <cuda_runtime.h>
#include <cuda_bf16.h>
#include <math.h>
#include <stdint.h>

#define BATCH 8192
#define DIM 256
#define KCAT 768                      // [hi | hi | lo] / [hi | lo | hi]
#define RCHUNK 32
#define ROWS_PER_CHUNK (BATCH / RCHUNK)

// GEMM tiling
#define TM 256
#define TN 128
#define KC 32                         // bf16 per K stage
#define NCHUNK (KCAT / KC)            // 24
#define ROWPITCH 80                   // bytes per smem row (32 bf16 = 64B, pad to 80)
#define STAGE_BYTES ((TM + TN) * ROWPITCH)   // 30720
#define NSTAGES 3
#define SMEM_TOTAL (STAGE_BYTES * NSTAGES)   // 92160

// Scratch (device globals: allocation-free per harness rules)
static __device__ float g_sim[(size_t)BATCH * BATCH];        // 256 MB
static __device__ __nv_bfloat16 g_Acat[(size_t)BATCH * KCAT];
static __device__ __nv_bfloat16 g_Bcat[(size_t)BATCH * KCAT];
static __device__ float g_thr[BATCH];
static __device__ float g_diag[BATCH];
static __device__ float g_rowlse[BATCH];
static __device__ float g_collse[BATCH];
static __device__ float g_pm[RCHUNK * BATCH];
static __device__ float g_ps[RCHUNK * BATCH];

// ---------------------------------------------------------------------------
// helpers
// ---------------------------------------------------------------------------
__device__ __forceinline__ uint32_t smem_to_u32(const void* p) {
    uint32_t a;
    asm("{ .reg .u64 t; cvta.to.shared.u64 t, %1; cvt.u32.u64 %0, t; }"
        : "=r"(a) : "l"(p));
    return a;
}
__device__ __forceinline__ void cp_async16(uint32_t smem_addr, const void* gptr) {
    asm volatile("cp.async.cg.shared.global [%0], [%1], 16;"
        :: "r"(smem_addr), "l"(gptr));
}
#define CP_COMMIT() asm volatile("cp.async.commit_group;" ::: "memory")
#define CP_WAIT1()  asm volatile("cp.async.wait_group 1;" ::: "memory")

__device__ __forceinline__ void ldsm_x4(uint32_t& r0, uint32_t& r1,
                                        uint32_t& r2, uint32_t& r3, uint32_t addr) {
    asm volatile("ldmatrix.sync.aligned.m8n8.x4.shared.b16 {%0,%1,%2,%3}, [%4];"
                 : "=r"(r0), "=r"(r1), "=r"(r2), "=r"(r3) : "r"(addr));
}
__device__ __forceinline__ void mma_bf16(float* d, const uint32_t* a, const uint32_t* b) {
    asm volatile(
        "mma.sync.aligned.m16n8k16.row.col.f32.bf16.bf16.f32 "
        "{%0,%1,%2,%3}, {%4,%5,%6,%7}, {%8,%9}, {%0,%1,%2,%3};"
        : "+f"(d[0]), "+f"(d[1]), "+f"(d[2]), "+f"(d[3])
        : "r"(a[0]), "r"(a[1]), "r"(a[2]), "r"(a[3]), "r"(b[0]), "r"(b[1]));
}

// ---------------------------------------------------------------------------
// K0: bf16 split precompute.  A_cat = [hi, hi, lo],  B_cat = [hi, lo, hi]
// sim = A_cat @ B_cat^T = hi*hi + hi*lo + lo*hi  (drops only lo*lo ~ 2^-18)
// ---------------------------------------------------------------------------
__global__ __launch_bounds__(256) void split_kernel(const float* __restrict__ V,
                                                    const float* __restrict__ Tm)
{
    size_t idx = (size_t)blockIdx.x * 256 + threadIdx.x;
    if (idx >= (size_t)BATCH * DIM) return;
    size_t row = idx / DIM;
    size_t k = idx % DIM;

    float a = V[idx];
    __nv_bfloat16 ah = __float2bfloat16(a);
    __nv_bfloat16 al = __float2bfloat16(a - __bfloat162float(ah));
    __nv_bfloat16* Ar = g_Acat + row * KCAT;
    Ar[k] = ah; Ar[k + 256] = ah; Ar[k + 512] = al;

    float b = Tm[idx];
    __nv_bfloat16 bh = __float2bfloat16(b);
    __nv_bfloat16 bl = __float2bfloat16(b - __bfloat162float(bh));
    __nv_bfloat16* Br = g_Bcat + row * KCAT;
    Br[k] = bh; Br[k + 256] = bl; Br[k + 512] = bh;
}

// ---------------------------------------------------------------------------
// K1: HMMA (mma.sync bf16) GEMM.  CTA tile 256x128, 8 warps of 64x64,
// 3-stage cp.async pipeline, K = 768.
// ---------------------------------------------------------------------------
__global__ __launch_bounds__(256, 1) void mma_gemm_kernel()
{
    extern __shared__ char smem[];
    const uint32_t smem_base = smem_to_u32(smem);
    const int tid = threadIdx.x;
    const int wid = tid >> 5;
    const int lane = tid & 31;
    const int m0 = blockIdx.y * TM;
    const int n0 = blockIdx.x * TN;

    const int wm = (wid & 3) * 64;   // warp row offset in tile
    const int wn = (wid >> 2) * 64;  // warp col offset in tile

    const char* Ag = (const char*)g_Acat;
    const char* Bg = (const char*)g_Bcat;

    // stage loader: A rows [m0,m0+256) then B rows [n0,n0+128), 16B chunks
    auto load_stage = [&](int s) {
        const uint32_t sb = smem_base + (uint32_t)(s % NSTAGES) * STAGE_BYTES;
        const int kelem = s * KC;
        #pragma unroll
        for (int j = 0; j < 6; j++) {
            int c = tid + j * 256;                 // 0..1535
            if (c < 1024) {
                int row = c >> 2, q = c & 3;
                cp_async16(sb + row * ROWPITCH + q * 16,
                           Ag + ((size_t)(m0 + row) * KCAT + kelem + q * 8) * 2);
            } else {
                int c2 = c - 1024;
                int row = c2 >> 2, q = c2 & 3;
                cp_async16(sb + (TM + row) * ROWPITCH + q * 16,
                           Bg + ((size_t)(n0 + row) * KCAT + kelem + q * 8) * 2);
            }
        }
        CP_COMMIT();
    };

    float acc[4][8][4];
    #pragma unroll
    for (int mt = 0; mt < 4; mt++)
        #pragma unroll
        for (int nt = 0; nt < 8; nt++)
            #pragma unroll
            for (int e = 0; e < 4; e++) acc[mt][nt][e] = 0.f;

    load_stage(0);
    load_stage(1);

    for (int s = 0; s < NCHUNK; s++) {
        CP_WAIT1();
        __syncthreads();
        if (s + 2 < NCHUNK) load_stage(s + 2);

        const uint32_t sb = smem_base + (uint32_t)(s % NSTAGES) * STAGE_BYTES;
        const uint32_t Asb = sb;
        const uint32_t Bsb = sb + TM * ROWPITCH;

        #pragma unroll
        for (int ks = 0; ks < 2; ks++) {         // two k16 steps per 32-k chunk
            const int kb = ks * 32;              // byte offset of k16 step
            uint32_t a[4][4], b[8][2];
            #pragma unroll
            for (int mt = 0; mt < 4; mt++) {
                uint32_t addr = Asb + (wm + mt * 16 + (lane & 15)) * ROWPITCH
                              + kb + (lane >> 4) * 16;
                ldsm_x4(a[mt][0], a[mt][1], a[mt][2], a[mt][3], addr);
            }
            #pragma unroll
            for (int np = 0; np < 4; np++) {     // pairs of n-tiles
                int n = wn + np * 16 + (lane & 7) + ((lane >> 4) << 3);
                uint32_t addr = Bsb + n * ROWPITCH + kb + (((lane >> 3) & 1) << 4);
                ldsm_x4(b[np * 2][0], b[np * 2][1], b[np * 2 + 1][0], b[np * 2 + 1][1], addr);
            }
            #pragma unroll
            for (int mt = 0; mt < 4; mt++)
                #pragma unroll
                for (int nt = 0; nt < 8; nt++)
                    mma_bf16(acc[mt][nt], a[mt], b[nt]);
        }
        __syncthreads();
    }

    // Epilogue: scale by 1/T, float2 stores (4 adjacent lanes fill a 32B sector)
    const float inv_t = 1.0f / 0.07f;
    #pragma unroll
    for (int mt = 0; mt < 4; mt++) {
        #pragma unroll
        for (int h = 0; h < 2; h++) {
            int row = m0 + wm + mt * 16 + (lane >> 2) + h * 8;
            float* dst = g_sim + (size_t)row * BATCH + n0 + wn + (lane & 3) * 2;
            #pragma unroll
            for (int nt = 0; nt < 8; nt++) {
                float2 v;
                v.x = acc[mt][nt][h * 2 + 0] * inv_t;
                v.y = acc[mt][nt][h * 2 + 1] * inv_t;
                *(float2*)(dst + nt * 8) = v;
            }
        }
    }
}

// ---------------------------------------------------------------------------
// K2: per row -> diag, thr (4th largest off-diag), rowLSE of weighted logits
// ---------------------------------------------------------------------------
__device__ __forceinline__ void top4_insert(float x, float& t0, float& t1,
                                            float& t2, float& t3)
{
    if (x > t3) {
        if (x > t0)      { t3 = t2; t2 = t1; t1 = t0; t0 = x; }
        else if (x > t1) { t3 = t2; t2 = t1; t1 = x; }
        else if (x > t2) { t3 = t2; t2 = x; }
        else             { t3 = x; }
    }
}

__global__ __launch_bounds__(256) void rowstats_kernel()
{
    __shared__ float row[BATCH];                      // 32 KB
    __shared__ float r0s[256], r1s[256], r2s[256], r3s[256];
    __shared__ float red[256];
    const int i = blockIdx.x;
    const int tid = threadIdx.x;
    const float* src = g_sim + (size_t)i * BATCH;
    for (int j = tid; j < BATCH; j += 256) row[j] = src[j];
    __syncthreads();

    const float diag = row[i];

    float t0 = -3e38f, t1 = -3e38f, t2 = -3e38f, t3 = -3e38f;
    for (int j = tid; j < BATCH; j += 256) {
        float x = (j == i) ? -3.0e38f : row[j];
        top4_insert(x, t0, t1, t2, t3);
    }
    r0s[tid] = t0; r1s[tid] = t1; r2s[tid] = t2; r3s[tid] = t3;
    __syncthreads();
    for (int s = 128; s > 0; s >>= 1) {
        if (tid < s) {
            float u0 = r0s[tid], u1 = r1s[tid], u2 = r2s[tid], u3 = r3s[tid];
            top4_insert(r0s[tid + s], u0, u1, u2, u3);
            top4_insert(r1s[tid + s], u0, u1, u2, u3);
            top4_insert(r2s[tid + s], u0, u1, u2, u3);
            top4_insert(r3s[tid + s], u0, u1, u2, u3);
            r0s[tid] = u0; r1s[tid] = u1; r2s[tid] = u2; r3s[tid] = u3;
        }
        __syncthreads();
    }
    const float thr = r3s[0];

    float m = -3e38f;
    for (int j = tid; j < BATCH; j += 256) {
        float x = row[j];
        float v = (j == i) ? x : ((x >= thr) ? 2.0f * x : x);
        m = fmaxf(m, v);
    }
    red[tid] = m; __syncthreads();
    for (int s = 128; s > 0; s >>= 1) {
        if (tid < s) red[tid] = fmaxf(red[tid], red[tid + s]);
        __syncthreads();
    }
    m = red[0];
    __syncthreads();

    float ssum = 0.f;
    for (int j = tid; j < BATCH; j += 256) {
        float x = row[j];
        float v = (j == i) ? x : ((x >= thr) ? 2.0f * x : x);
        ssum += expf(v - m);
    }
    red[tid] = ssum; __syncthreads();
    for (int s = 128; s > 0; s >>= 1) {
        if (tid < s) red[tid] += red[tid + s];
        __syncthreads();
    }
    if (tid == 0) {
        g_rowlse[i] = m + logf(red[0]);
        g_diag[i] = diag;
        g_thr[i] = thr;
    }
}

// ---------------------------------------------------------------------------
// K3: partial column LSE over a 256-row chunk (online LSE per thread)
// ---------------------------------------------------------------------------
__global__ __launch_bounds__(256) void colpass_kernel()
{
    const int j = blockIdx.x * 256 + threadIdx.x;
    const int i0 = blockIdx.y * ROWS_PER_CHUNK;
    float m = -3e38f, s = 0.f;
    const float* p = g_sim + (size_t)i0 * BATCH + j;
    for (int r = 0; r < ROWS_PER_CHUNK; r++) {
        const int i = i0 + r;
        float x = *p;
        p += BATCH;
        float thr = __ldg(&g_thr[i]);
        float v = (j == i) ? x : ((x >= thr) ? 2.0f * x : x);
        if (v > m) { s = s * expf(m - v) + 1.0f; m = v; }
        else       { s += expf(v - m); }
    }
    g_pm[blockIdx.y * BATCH + j] = m;
    g_ps[blockIdx.y * BATCH + j] = s;
}

__global__ __launch_bounds__(256) void colmerge_kernel()
{
    const int j = blockIdx.x * 256 + threadIdx.x;
    float M = -3e38f;
#pragma unroll
    for (int c = 0; c < RCHUNK; c++) M = fmaxf(M, g_pm[c * BATCH + j]);
    float S = 0.f;
#pragma unroll
    for (int c = 0; c < RCHUNK; c++) S += g_ps[c * BATCH + j] * expf(g_pm[c * BATCH + j] - M);
    g_collse[j] = M + logf(S);
}

// ---------------------------------------------------------------------------
// K4: loss = sum_i [(rowLSE_i - diag_i) + (colLSE_i - diag_i)] / (2B)
// ---------------------------------------------------------------------------
__global__ __launch_bounds__(256) void finalize_kernel(float* __restrict__ out)
{
    __shared__ float red[256];
    const int tid = threadIdx.x;
    float acc = 0.f;
    for (int i = tid; i < BATCH; i += 256)
        acc += (g_rowlse[i] - g_diag[i]) + (g_collse[i] - g_diag[i]);
    red[tid] = acc; __syncthreads();
    for (int s = 128; s > 0; s >>= 1) {
        if (tid < s) red[tid] += red[tid + s];
        __syncthreads();
    }
    if (tid == 0) out[0] = red[0] / (2.0f * (float)BATCH);
}

extern "C" void kernel_launch(void* const* d_in, const int* in_sizes, int n_in,
                              void* d_out, int out_size)
{
    (void)in_sizes; (void)n_in; (void)out_size;
    const float* V  = (const float*)d_in[0];   // vision_embed [8192, 256]
    const float* Tm = (const float*)d_in[1];   // text_embed   [8192, 256]
    float* out = (float*)d_out;

    cudaFuncSetAttribute(mma_gemm_kernel,
                         cudaFuncAttributeMaxDynamicSharedMemorySize, SMEM_TOTAL);

    split_kernel<<<(BATCH * DIM + 255) / 256, 256>>>(V, Tm);
    mma_gemm_kernel<<<dim3(BATCH / TN, BATCH / TM), 256, SMEM_TOTAL>>>();
    rowstats_kernel<<<BATCH, 256>>>();
    colpass_kernel<<<dim3(BATCH / 256, RCHUNK), 256>>>();
    colmerge_kernel<<<BATCH / 256, 256>>>();
    finalize_kernel<<<1, 256>>>(out);
}